// round 2
// baseline (speedup 1.0000x reference)
#include <cuda_runtime.h>
#include <math.h>

// Shapes (fixed by the problem): B=32, T=2000, D=512, halves of 256, 3H=768.
#define M_TOTAL   64000          // B*T
#define D_FULL    512
#define D_HALF    256
#define N_COLS    768            // 3*H per half
#define BM 128
#define BN 128
#define BK 8
#define TM 8
#define TN 8

// Scratch (device globals: allocation-free per harness rules). 3 x 131 MB.
__device__ float g_xt[M_TOTAL * D_FULL];
__device__ float g_f [M_TOTAL * D_FULL];
__device__ float g_r [M_TOTAL * D_FULL];

__device__ __forceinline__ float sigmoidf_(float v) {
    return 1.0f / (1.0f + __expf(-v));
}

// ---------------------------------------------------------------------------
// Kernel 1: U = x_half @ W (per half), fused bias+sigmoid on f/r columns.
// Tile 128x128x8, 256 threads, 8x8 per thread. All dims divide exactly.
// Column regions per half: [0,256)=x_tilde, [256,512)=f, [512,768)=r.
// BN=128 tiles align with 256-wide regions -> region uniform per block.
// ---------------------------------------------------------------------------
__global__ __launch_bounds__(256, 2)
void gemm_act_kernel(const float* __restrict__ x,
                     const float* __restrict__ W1, const float* __restrict__ bf1,
                     const float* __restrict__ br1,
                     const float* __restrict__ W2, const float* __restrict__ bf2,
                     const float* __restrict__ br2)
{
    const int s    = blockIdx.z;      // half index 0/1
    const int nblk = blockIdx.x;      // 0..5
    const int mblk = blockIdx.y;      // 0..499

    const float* W  = s ? W2  : W1;
    const float* bf = s ? bf2 : bf1;
    const float* br = s ? br2 : br1;

    __shared__ float As[BK][BM];      // transposed A tile
    __shared__ float Bs[BK][BN];

    const int tid = threadIdx.x;

    // A-tile load map: 128 rows x 8 cols = 256 float4 (2 per row)
    const int arow  = tid >> 1;          // 0..127
    const int acol4 = (tid & 1) * 4;     // 0 or 4
    // B-tile load map: 8 rows x 128 cols = 8 x 32 float4
    const int brow  = tid >> 5;          // 0..7
    const int bcol4 = (tid & 31) * 4;

    const float* Aptr = x + (size_t)(mblk * BM) * D_FULL + s * D_HALF;
    const float* Bptr = W + nblk * BN;

    const int tr = tid >> 4;   // 0..15
    const int tc = tid & 15;   // 0..15

    float acc[TM][TN];
    #pragma unroll
    for (int i = 0; i < TM; i++)
        #pragma unroll
        for (int j = 0; j < TN; j++) acc[i][j] = 0.0f;

    #pragma unroll 1
    for (int kt = 0; kt < D_HALF / BK; kt++) {
        // load A tile (transpose into As[k][m])
        float4 a = *(const float4*)(Aptr + (size_t)arow * D_FULL + kt * BK + acol4);
        As[acol4 + 0][arow] = a.x;
        As[acol4 + 1][arow] = a.y;
        As[acol4 + 2][arow] = a.z;
        As[acol4 + 3][arow] = a.w;
        // load B tile
        float4 b = *(const float4*)(Bptr + (size_t)(kt * BK + brow) * N_COLS + bcol4);
        *(float4*)&Bs[brow][bcol4] = b;
        __syncthreads();

        #pragma unroll
        for (int k = 0; k < BK; k++) {
            float ra[TM], rb[TN];
            #pragma unroll
            for (int i = 0; i < TM; i++) ra[i] = As[k][tr * TM + i];
            #pragma unroll
            for (int j = 0; j < TN; j++) rb[j] = Bs[k][tc * TN + j];
            #pragma unroll
            for (int i = 0; i < TM; i++)
                #pragma unroll
                for (int j = 0; j < TN; j++)
                    acc[i][j] = fmaf(ra[i], rb[j], acc[i][j]);
        }
        __syncthreads();
    }

    // Epilogue
    const int n0     = nblk * BN;            // 0,128,256,384,512,640
    const int region = n0 >> 8;              // 0=x_tilde, 1=f, 2=r
    float* dst = (region == 0) ? g_xt : ((region == 1) ? g_f : g_r);
    const float* bias = (region == 1) ? bf : br;

    #pragma unroll
    for (int i = 0; i < TM; i++) {
        const int m = mblk * BM + tr * TM + i;
        #pragma unroll
        for (int j4 = 0; j4 < TN; j4 += 4) {
            const int n = n0 + tc * TN + j4;        // column within [0,768)
            const int h = n & (D_HALF - 1);         // channel within half
            const int c = s * D_HALF + h;           // global channel
            float4 v;
            v.x = acc[i][j4 + 0];
            v.y = acc[i][j4 + 1];
            v.z = acc[i][j4 + 2];
            v.w = acc[i][j4 + 3];
            if (region != 0) {
                v.x = sigmoidf_(v.x + bias[h + 0]);
                v.y = sigmoidf_(v.y + bias[h + 1]);
                v.z = sigmoidf_(v.z + bias[h + 2]);
                v.w = sigmoidf_(v.w + bias[h + 3]);
            }
            *(float4*)&dst[(size_t)m * D_FULL + c] = v;
        }
    }
}

// ---------------------------------------------------------------------------
// Kernel 2: time scan + highway. One thread per (batch, channel).
// c_t = f*c + (1-f)*xt ;  out = r*c + (1-r)*x
// Adjacent threads = adjacent channels -> fully coalesced per time step.
// ---------------------------------------------------------------------------
__global__ __launch_bounds__(256)
void scan_kernel(const float* __restrict__ x, float* __restrict__ out, int T)
{
    const int idx = blockIdx.x * blockDim.x + threadIdx.x;  // 0..16383
    const int b = idx >> 9;          // / 512
    const int c = idx & (D_FULL - 1);

    const size_t base = (size_t)b * T * D_FULL + c;
    const float* pf  = g_f  + base;
    const float* pxt = g_xt + base;
    const float* pr  = g_r  + base;
    const float* px  = x    + base;
    float*       po  = out  + base;

    float cacc = 0.0f;
    #pragma unroll 4
    for (int t = 0; t < T; t++) {
        const size_t off = (size_t)t * D_FULL;
        const float f  = pf [off];
        const float xt = pxt[off];
        const float r  = pr [off];
        const float xv = px [off];
        cacc = fmaf(f, cacc, (1.0f - f) * xt);
        po[off] = fmaf(r, cacc, (1.0f - r) * xv);
    }
}

// ---------------------------------------------------------------------------
extern "C" void kernel_launch(void* const* d_in, const int* in_sizes, int n_in,
                              void* d_out, int out_size)
{
    const float* x   = (const float*)d_in[0];
    const float* W1  = (const float*)d_in[1];
    const float* bf1 = (const float*)d_in[2];
    const float* br1 = (const float*)d_in[3];
    const float* W2  = (const float*)d_in[4];
    const float* bf2 = (const float*)d_in[5];
    const float* br2 = (const float*)d_in[6];
    float* out = (float*)d_out;

    (void)n_in; (void)in_sizes; (void)out_size;

    dim3 grid(N_COLS / BN, M_TOTAL / BM, 2);   // (6, 500, 2)
    gemm_act_kernel<<<grid, 256>>>(x, W1, bf1, br1, W2, bf2, br2);

    const int T = M_TOTAL / 32;                // 2000
    scan_kernel<<<(32 * D_FULL) / 256, 256>>>(x, out, T);
}

// round 3
// speedup vs baseline: 1.4076x; 1.4076x over previous
#include <cuda_runtime.h>
#include <math.h>

// Shapes (fixed by the problem): B=32, T=2000, D=512, halves of 256, 3H=768.
#define M_TOTAL   64000          // B*T
#define B_SZ      32
#define T_LEN     2000
#define D_FULL    512
#define D_HALF    256
#define N_COLS    768            // 3*H per half
#define BM 128
#define BN 128
#define BK 8
#define TM 8
#define TN 8

// Scan chunking
#define NCHUNK 40
#define CLEN   50                // NCHUNK*CLEN == T_LEN

// Scratch (device globals: allocation-free per harness rules).
__device__ float g_xt[M_TOTAL * D_FULL];
__device__ float g_f [M_TOTAL * D_FULL];
__device__ float g_r [M_TOTAL * D_FULL];
// chunk summaries / carries: [b][chunk][c]
__device__ float g_P  [B_SZ * NCHUNK * D_FULL];
__device__ float g_C  [B_SZ * NCHUNK * D_FULL];
__device__ float g_cin[B_SZ * NCHUNK * D_FULL];

__device__ __forceinline__ float sigmoidf_(float v) {
    return 1.0f / (1.0f + __expf(-v));
}

// ---------------------------------------------------------------------------
// Kernel 1: U = x_half @ W (per half), fused bias+sigmoid on f/r columns.
// (unchanged from R1 — GEMM optimization deferred; isolating scan change)
// ---------------------------------------------------------------------------
__global__ __launch_bounds__(256, 2)
void gemm_act_kernel(const float* __restrict__ x,
                     const float* __restrict__ W1, const float* __restrict__ bf1,
                     const float* __restrict__ br1,
                     const float* __restrict__ W2, const float* __restrict__ bf2,
                     const float* __restrict__ br2)
{
    const int s    = blockIdx.z;
    const int nblk = blockIdx.x;
    const int mblk = blockIdx.y;

    const float* W  = s ? W2  : W1;
    const float* bf = s ? bf2 : bf1;
    const float* br = s ? br2 : br1;

    __shared__ float As[BK][BM];
    __shared__ float Bs[BK][BN];

    const int tid = threadIdx.x;

    const int arow  = tid >> 1;
    const int acol4 = (tid & 1) * 4;
    const int brow  = tid >> 5;
    const int bcol4 = (tid & 31) * 4;

    const float* Aptr = x + (size_t)(mblk * BM) * D_FULL + s * D_HALF;
    const float* Bptr = W + nblk * BN;

    const int tr = tid >> 4;
    const int tc = tid & 15;

    float acc[TM][TN];
    #pragma unroll
    for (int i = 0; i < TM; i++)
        #pragma unroll
        for (int j = 0; j < TN; j++) acc[i][j] = 0.0f;

    #pragma unroll 1
    for (int kt = 0; kt < D_HALF / BK; kt++) {
        float4 a = *(const float4*)(Aptr + (size_t)arow * D_FULL + kt * BK + acol4);
        As[acol4 + 0][arow] = a.x;
        As[acol4 + 1][arow] = a.y;
        As[acol4 + 2][arow] = a.z;
        As[acol4 + 3][arow] = a.w;
        float4 b = *(const float4*)(Bptr + (size_t)(kt * BK + brow) * N_COLS + bcol4);
        *(float4*)&Bs[brow][bcol4] = b;
        __syncthreads();

        #pragma unroll
        for (int k = 0; k < BK; k++) {
            float ra[TM], rb[TN];
            #pragma unroll
            for (int i = 0; i < TM; i++) ra[i] = As[k][tr * TM + i];
            #pragma unroll
            for (int j = 0; j < TN; j++) rb[j] = Bs[k][tc * TN + j];
            #pragma unroll
            for (int i = 0; i < TM; i++)
                #pragma unroll
                for (int j = 0; j < TN; j++)
                    acc[i][j] = fmaf(ra[i], rb[j], acc[i][j]);
        }
        __syncthreads();
    }

    const int n0     = nblk * BN;
    const int region = n0 >> 8;
    float* dst = (region == 0) ? g_xt : ((region == 1) ? g_f : g_r);
    const float* bias = (region == 1) ? bf : br;

    #pragma unroll
    for (int i = 0; i < TM; i++) {
        const int m = mblk * BM + tr * TM + i;
        #pragma unroll
        for (int j4 = 0; j4 < TN; j4 += 4) {
            const int n = n0 + tc * TN + j4;
            const int h = n & (D_HALF - 1);
            const int c = s * D_HALF + h;
            float4 v;
            v.x = acc[i][j4 + 0];
            v.y = acc[i][j4 + 1];
            v.z = acc[i][j4 + 2];
            v.w = acc[i][j4 + 3];
            if (region != 0) {
                v.x = sigmoidf_(v.x + bias[h + 0]);
                v.y = sigmoidf_(v.y + bias[h + 1]);
                v.z = sigmoidf_(v.z + bias[h + 2]);
                v.w = sigmoidf_(v.w + bias[h + 3]);
            }
            *(float4*)&dst[(size_t)m * D_FULL + c] = v;
        }
    }
}

// ---------------------------------------------------------------------------
// Scan phase 1: per (b, chunk, c) compute local affine summary (P, C):
//   c_out = P * c_in + C, with P = prod f_t and C = local scan from c=0.
// Block = 256 threads = half the channels; grid (2, NCHUNK, B).
// ---------------------------------------------------------------------------
__global__ __launch_bounds__(256)
void scan_phase1(void)
{
    const int c     = blockIdx.x * 256 + threadIdx.x;   // 0..511
    const int chunk = blockIdx.y;
    const int b     = blockIdx.z;

    const size_t base = ((size_t)b * T_LEN + (size_t)chunk * CLEN) * D_FULL + c;
    const float* pf  = g_f  + base;
    const float* pxt = g_xt + base;

    float P = 1.0f, C = 0.0f;
    #pragma unroll 5
    for (int t = 0; t < CLEN; t++) {
        const size_t off = (size_t)t * D_FULL;
        const float f  = pf [off];
        const float xt = pxt[off];
        C = fmaf(f, C, (1.0f - f) * xt);
        P *= f;
    }
    const size_t sidx = ((size_t)b * NCHUNK + chunk) * D_FULL + c;
    g_P[sidx] = P;
    g_C[sidx] = C;
}

// ---------------------------------------------------------------------------
// Scan phase 2: serial scan over chunk summaries per (b, c) -> carry-in.
// 16384 threads; adjacent threads adjacent c (coalesced).
// ---------------------------------------------------------------------------
__global__ __launch_bounds__(256)
void scan_phase2(void)
{
    const int idx = blockIdx.x * 256 + threadIdx.x;     // 0..16383
    const int b = idx >> 9;
    const int c = idx & (D_FULL - 1);

    float carry = 0.0f;
    #pragma unroll
    for (int k = 0; k < NCHUNK; k++) {
        const size_t sidx = ((size_t)b * NCHUNK + k) * D_FULL + c;
        g_cin[sidx] = carry;
        carry = fmaf(g_P[sidx], carry, g_C[sidx]);
    }
}

// ---------------------------------------------------------------------------
// Scan phase 3: rerun recurrence from correct carry-in; fused highway output.
//   c_t = f*c + (1-f)*xt ;  out = r*c + (1-r)*x
// ---------------------------------------------------------------------------
__global__ __launch_bounds__(256)
void scan_phase3(const float* __restrict__ x, float* __restrict__ out)
{
    const int c     = blockIdx.x * 256 + threadIdx.x;
    const int chunk = blockIdx.y;
    const int b     = blockIdx.z;

    const size_t base = ((size_t)b * T_LEN + (size_t)chunk * CLEN) * D_FULL + c;
    const float* pf  = g_f  + base;
    const float* pxt = g_xt + base;
    const float* pr  = g_r  + base;
    const float* px  = x    + base;
    float*       po  = out  + base;

    float cacc = g_cin[((size_t)b * NCHUNK + chunk) * D_FULL + c];

    #pragma unroll 5
    for (int t = 0; t < CLEN; t++) {
        const size_t off = (size_t)t * D_FULL;
        const float f  = pf [off];
        const float xt = pxt[off];
        const float r  = pr [off];
        const float xv = px [off];
        cacc = fmaf(f, cacc, (1.0f - f) * xt);
        po[off] = fmaf(r, cacc, (1.0f - r) * xv);
    }
}

// ---------------------------------------------------------------------------
extern "C" void kernel_launch(void* const* d_in, const int* in_sizes, int n_in,
                              void* d_out, int out_size)
{
    const float* x   = (const float*)d_in[0];
    const float* W1  = (const float*)d_in[1];
    const float* bf1 = (const float*)d_in[2];
    const float* br1 = (const float*)d_in[3];
    const float* W2  = (const float*)d_in[4];
    const float* bf2 = (const float*)d_in[5];
    const float* br2 = (const float*)d_in[6];
    float* out = (float*)d_out;

    (void)n_in; (void)in_sizes; (void)out_size;

    dim3 grid(N_COLS / BN, M_TOTAL / BM, 2);   // (6, 500, 2)
    gemm_act_kernel<<<grid, 256>>>(x, W1, bf1, br1, W2, bf2, br2);

    dim3 sgrid(2, NCHUNK, B_SZ);               // (2, 40, 32) = 2560 blocks
    scan_phase1<<<sgrid, 256>>>();
    scan_phase2<<<(B_SZ * D_FULL) / 256, 256>>>();
    scan_phase3<<<sgrid, 256>>>(x, out);
}

// round 5
// speedup vs baseline: 3.1732x; 2.2543x over previous
#include <cuda_runtime.h>
#include <cstdint>
#include <math.h>

// Shapes (fixed): B=32, T=2000, D=512, halves of 256, 3H=768.
#define M_TOTAL   64000
#define B_SZ      32
#define T_LEN     2000
#define D_FULL    512
#define D_HALF    256
#define N_COLS    768

// Scan chunking
#define NCHUNK 40
#define CLEN   50

// GEMM tiling (mma.sync tf32)
#define BM 128
#define BN 128
#define BK 16
#define NKT (D_HALF / BK)        // 16 k-tiles
#define SA_STR 20                // padded floats per A row (BK=16 + 4)
#define SB_STR 132               // padded floats per B row (BN=128 + 4)

// Scratch (device globals: allocation-free per harness rules).
__device__ float g_xt[M_TOTAL * D_FULL];
__device__ float g_f [M_TOTAL * D_FULL];
__device__ float g_r [M_TOTAL * D_FULL];
__device__ float g_P  [B_SZ * NCHUNK * D_FULL];
__device__ float g_C  [B_SZ * NCHUNK * D_FULL];
__device__ float g_cin[B_SZ * NCHUNK * D_FULL];

__device__ __forceinline__ float sigmoidf_(float v) {
    return 1.0f / (1.0f + __expf(-v));
}

__device__ __forceinline__ uint32_t smem_u32(const void* p) {
    uint32_t a;
    asm("{ .reg .u64 t; cvta.to.shared.u64 t, %1; cvt.u32.u64 %0, t; }"
        : "=r"(a) : "l"(p));
    return a;
}

__device__ __forceinline__ uint32_t to_tf32(float v) {
    uint32_t d;
    asm("cvt.rna.tf32.f32 %0, %1;" : "=r"(d) : "f"(v));
    return d;
}

__device__ __forceinline__ void cp_async16(uint32_t smem_dst, const void* gptr) {
    asm volatile("cp.async.ca.shared.global [%0], [%1], 16;"
                 :: "r"(smem_dst), "l"(gptr) : "memory");
}
__device__ __forceinline__ void cp_async_commit() {
    asm volatile("cp.async.commit_group;" ::: "memory");
}
__device__ __forceinline__ void cp_async_wait_all() {
    asm volatile("cp.async.wait_group 0;" ::: "memory");
}

__device__ __forceinline__ void mma_tf32(float* c, const uint32_t* a, const uint32_t* b) {
    asm volatile(
        "mma.sync.aligned.m16n8k8.row.col.f32.tf32.tf32.f32 "
        "{%0,%1,%2,%3}, {%4,%5,%6,%7}, {%8,%9}, {%0,%1,%2,%3};"
        : "+f"(c[0]), "+f"(c[1]), "+f"(c[2]), "+f"(c[3])
        : "r"(a[0]), "r"(a[1]), "r"(a[2]), "r"(a[3]), "r"(b[0]), "r"(b[1]));
}

// ---------------------------------------------------------------------------
// Kernel 1: tf32 mma.sync GEMM, 128x128 block, BK=16 double-buffered cp.async.
// 8 warps = 2(m) x 4(n); warp tile 64x32 = 4x4 frags of m16n8k8.
// Fused bias+sigmoid epilogue writing g_xt/g_f/g_r.
// Grid: (12, 500) — x encodes (half, nblk); y = mblk. 256 threads.
// ---------------------------------------------------------------------------
__global__ __launch_bounds__(256, 2)
void gemm_mma_kernel(const float* __restrict__ x,
                     const float* __restrict__ W1, const float* __restrict__ bf1,
                     const float* __restrict__ br1,
                     const float* __restrict__ W2, const float* __restrict__ bf2,
                     const float* __restrict__ br2)
{
    const int s    = blockIdx.x / 6;     // half 0/1
    const int nblk = blockIdx.x % 6;     // 0..5
    const int mblk = blockIdx.y;         // 0..499

    const float* W  = s ? W2  : W1;
    const float* bf = s ? bf2 : bf1;
    const float* br = s ? br2 : br1;

    __shared__ float sA[2][BM * SA_STR];   // 2 x 10240 B
    __shared__ float sB[2][BK * SB_STR];   // 2 x 8448 B

    const int tid    = threadIdx.x;
    const int wid    = tid >> 5;
    const int lid    = tid & 31;
    const int gid    = lid >> 2;         // group id 0..7
    const int tig    = lid & 3;          // thread-in-group 0..3
    const int warp_m = wid >> 2;         // 0..1
    const int warp_n = wid & 3;          // 0..3

    const float* Agbl = x + (size_t)(mblk * BM) * D_FULL + s * D_HALF;
    const float* Bgbl = W + nblk * BN;

    // cp.async maps (2 chunks of 16B per thread for each tile)
    const int a_row = tid >> 2;                  // with +64 for second chunk? no:
    // A: 512 chunks: idx = tid + 256*j ; row = idx>>2, c4 = idx&3
    // B: 512 chunks: idx = tid + 256*j ; k = idx>>5, n4 = idx&31

    auto prefetch = [&](int kt, int buf) {
        #pragma unroll
        for (int j = 0; j < 2; j++) {
            const int idx = tid + 256 * j;
            const int row = idx >> 2;
            const int c4  = idx & 3;
            cp_async16(smem_u32(&sA[buf][row * SA_STR + c4 * 4]),
                       Agbl + (size_t)row * D_FULL + kt * BK + c4 * 4);
        }
        #pragma unroll
        for (int j = 0; j < 2; j++) {
            const int idx = tid + 256 * j;
            const int k   = idx >> 5;
            const int n4  = idx & 31;
            cp_async16(smem_u32(&sB[buf][k * SB_STR + n4 * 4]),
                       Bgbl + (size_t)(kt * BK + k) * N_COLS + n4 * 4);
        }
        cp_async_commit();
    };

    float acc[4][4][4];
    #pragma unroll
    for (int mi = 0; mi < 4; mi++)
        #pragma unroll
        for (int ni = 0; ni < 4; ni++)
            #pragma unroll
            for (int q = 0; q < 4; q++) acc[mi][ni][q] = 0.0f;

    prefetch(0, 0);

    #pragma unroll 1
    for (int kt = 0; kt < NKT; kt++) {
        cp_async_wait_all();
        __syncthreads();
        if (kt + 1 < NKT) prefetch(kt + 1, (kt + 1) & 1);

        const float* A = sA[kt & 1];
        const float* B = sB[kt & 1];

        #pragma unroll
        for (int ks = 0; ks < BK; ks += 8) {
            uint32_t af[4][4], bfr[4][2];
            #pragma unroll
            for (int mi = 0; mi < 4; mi++) {
                const int m = warp_m * 64 + mi * 16;
                af[mi][0] = to_tf32(A[(m + gid    ) * SA_STR + ks + tig    ]);
                af[mi][1] = to_tf32(A[(m + gid + 8) * SA_STR + ks + tig    ]);
                af[mi][2] = to_tf32(A[(m + gid    ) * SA_STR + ks + tig + 4]);
                af[mi][3] = to_tf32(A[(m + gid + 8) * SA_STR + ks + tig + 4]);
            }
            #pragma unroll
            for (int ni = 0; ni < 4; ni++) {
                const int n = warp_n * 32 + ni * 8;
                bfr[ni][0] = to_tf32(B[(ks + tig    ) * SB_STR + n + gid]);
                bfr[ni][1] = to_tf32(B[(ks + tig + 4) * SB_STR + n + gid]);
            }
            #pragma unroll
            for (int mi = 0; mi < 4; mi++)
                #pragma unroll
                for (int ni = 0; ni < 4; ni++)
                    mma_tf32(acc[mi][ni], af[mi], bfr[ni]);
        }
    }

    // ---- epilogue: fused bias + sigmoid, float2 stores ----
    const int n0      = nblk * BN;           // 0..640
    const int region  = n0 >> 8;             // 0=xt, 1=f, 2=r
    float* dst        = (region == 0) ? g_xt : ((region == 1) ? g_f : g_r);
    const float* bias = (region == 1) ? bf : br;

    #pragma unroll
    for (int mi = 0; mi < 4; mi++) {
        const int row0 = mblk * BM + warp_m * 64 + mi * 16 + gid;
        #pragma unroll
        for (int ni = 0; ni < 4; ni++) {
            const int h = (n0 & (D_HALF - 1)) + warp_n * 32 + ni * 8 + 2 * tig;
            float v0 = acc[mi][ni][0], v1 = acc[mi][ni][1];
            float v2 = acc[mi][ni][2], v3 = acc[mi][ni][3];
            if (region != 0) {
                const float b0 = __ldg(bias + h), b1 = __ldg(bias + h + 1);
                v0 = sigmoidf_(v0 + b0);
                v1 = sigmoidf_(v1 + b1);
                v2 = sigmoidf_(v2 + b0);
                v3 = sigmoidf_(v3 + b1);
            }
            const size_t col = (size_t)s * D_HALF + h;
            *(float2*)(dst + (size_t)row0 * D_FULL + col)       = make_float2(v0, v1);
            *(float2*)(dst + (size_t)(row0 + 8) * D_FULL + col) = make_float2(v2, v3);
        }
    }
}

// ---------------------------------------------------------------------------
// Scan phase 1: per (b, chunk, c) local affine summary (P, C).
// ---------------------------------------------------------------------------
__global__ __launch_bounds__(256)
void scan_phase1(void)
{
    const int c     = blockIdx.x * 256 + threadIdx.x;
    const int chunk = blockIdx.y;
    const int b     = blockIdx.z;

    const size_t base = ((size_t)b * T_LEN + (size_t)chunk * CLEN) * D_FULL + c;
    const float* pf  = g_f  + base;
    const float* pxt = g_xt + base;

    float P = 1.0f, C = 0.0f;
    #pragma unroll 5
    for (int t = 0; t < CLEN; t++) {
        const size_t off = (size_t)t * D_FULL;
        const float f  = pf [off];
        const float xt = pxt[off];
        C = fmaf(f, C, (1.0f - f) * xt);
        P *= f;
    }
    const size_t sidx = ((size_t)b * NCHUNK + chunk) * D_FULL + c;
    g_P[sidx] = P;
    g_C[sidx] = C;
}

// ---------------------------------------------------------------------------
// Scan phase 2: serial scan over chunk summaries -> carry-in per chunk.
// ---------------------------------------------------------------------------
__global__ __launch_bounds__(256)
void scan_phase2(void)
{
    const int idx = blockIdx.x * 256 + threadIdx.x;
    const int b = idx >> 9;
    const int c = idx & (D_FULL - 1);

    float carry = 0.0f;
    #pragma unroll
    for (int k = 0; k < NCHUNK; k++) {
        const size_t sidx = ((size_t)b * NCHUNK + k) * D_FULL + c;
        g_cin[sidx] = carry;
        carry = fmaf(g_P[sidx], carry, g_C[sidx]);
    }
}

// ---------------------------------------------------------------------------
// Scan phase 3: recurrence from carry-in; fused highway output.
// ---------------------------------------------------------------------------
__global__ __launch_bounds__(256)
void scan_phase3(const float* __restrict__ x, float* __restrict__ out)
{
    const int c     = blockIdx.x * 256 + threadIdx.x;
    const int chunk = blockIdx.y;
    const int b     = blockIdx.z;

    const size_t base = ((size_t)b * T_LEN + (size_t)chunk * CLEN) * D_FULL + c;
    const float* pf  = g_f  + base;
    const float* pxt = g_xt + base;
    const float* pr  = g_r  + base;
    const float* px  = x    + base;
    float*       po  = out  + base;

    float cacc = g_cin[((size_t)b * NCHUNK + chunk) * D_FULL + c];

    #pragma unroll 5
    for (int t = 0; t < CLEN; t++) {
        const size_t off = (size_t)t * D_FULL;
        const float f  = pf [off];
        const float xt = pxt[off];
        const float r  = pr [off];
        const float xv = px [off];
        cacc = fmaf(f, cacc, (1.0f - f) * xt);
        po[off] = fmaf(r, cacc, (1.0f - r) * xv);
    }
}

// ---------------------------------------------------------------------------
extern "C" void kernel_launch(void* const* d_in, const int* in_sizes, int n_in,
                              void* d_out, int out_size)
{
    const float* x   = (const float*)d_in[0];
    const float* W1  = (const float*)d_in[1];
    const float* bf1 = (const float*)d_in[2];
    const float* br1 = (const float*)d_in[3];
    const float* W2  = (const float*)d_in[4];
    const float* bf2 = (const float*)d_in[5];
    const float* br2 = (const float*)d_in[6];
    float* out = (float*)d_out;

    (void)n_in; (void)in_sizes; (void)out_size;

    dim3 ggrid(12, M_TOTAL / BM);              // (12, 500)
    gemm_mma_kernel<<<ggrid, 256>>>(x, W1, bf1, br1, W2, bf2, br2);

    dim3 sgrid(2, NCHUNK, B_SZ);               // (2, 40, 32)
    scan_phase1<<<sgrid, 256>>>();
    scan_phase2<<<(B_SZ * D_FULL) / 256, 256>>>();
    scan_phase3<<<sgrid, 256>>>(x, out);
}